// round 4
// baseline (speedup 1.0000x reference)
#include <cuda_runtime.h>
#include <cstddef>
#include <cstdint>

#define N_PTS   20000
#define E_EDGES 320000
#define KNN     16
#define FEAT    64
#define R_REP   4

// ---------------- scratch (static device globals; allocation-free) ----------
__device__ float g_x1[(size_t)N_PTS * FEAT];          // 5.12 MB
__device__ float g_sq[N_PTS];
__device__ int   g_nbr[(size_t)N_PTS * KNN];          // 1.28 MB
__device__ float g_x2[(size_t)N_PTS * FEAT];          // 5.12 MB

// ---------------- helpers ---------------------------------------------------
__device__ __forceinline__ unsigned enc_f(float f) {
    unsigned u = __float_as_uint(f);
    return (u & 0x80000000u) ? ~u : (u | 0x80000000u);
}

// ---------------- zero x1 ----------------------------------------------------
__global__ void k_zero_x1() {
    int i = blockIdx.x * blockDim.x + threadIdx.x;
    if (i < N_PTS * FEAT) g_x1[i] = 0.f;
}

// ---------------- stage 1: edge MLP (6->64->64, ReLU) + segment_max ---------
__global__ void __launch_bounds__(256) k_edge(
    const float* __restrict__ pts, const int* __restrict__ ei,
    const float* __restrict__ W1a, const float* __restrict__ b1a,
    const float* __restrict__ W1b, const float* __restrict__ b1b)
{
    __shared__ float sW1a[6 * 64];        // 1.5 KB
    __shared__ float sW1b[64 * 64];       // 16 KB
    __shared__ float sh1[64][66];         // 16.9 KB
    int t = threadIdx.x;
    for (int i = t; i < 6 * 64 / 4; i += 256)
        ((float4*)sW1a)[i] = ((const float4*)W1a)[i];
    for (int i = t; i < 64 * 64 / 4; i += 256)
        ((float4*)sW1b)[i] = ((const float4*)W1b)[i];

    int e  = t >> 2;              // edge within block (0..63)
    int o0 = (t & 3) * 16;        // 16 outputs per thread
    int eg = blockIdx.x * 64 + e;
    int s  = ei[eg];              // src
    int d  = ei[E_EDGES + eg];    // dst
    float xi0 = pts[d * 3 + 0], xi1 = pts[d * 3 + 1], xi2 = pts[d * 3 + 2];
    float in6[6];
    in6[0] = xi0; in6[1] = xi1; in6[2] = xi2;
    in6[3] = pts[s * 3 + 0] - xi0;
    in6[4] = pts[s * 3 + 1] - xi1;
    in6[5] = pts[s * 3 + 2] - xi2;
    __syncthreads();

    float acc[16];
#pragma unroll
    for (int u = 0; u < 16; u++) acc[u] = __ldg(&b1a[o0 + u]);
#pragma unroll
    for (int k = 0; k < 6; k++) {
        float x = in6[k];
#pragma unroll
        for (int v = 0; v < 4; v++) {
            float4 w = *(const float4*)&sW1a[k * 64 + o0 + v * 4];
            acc[v*4+0] = fmaf(x, w.x, acc[v*4+0]);
            acc[v*4+1] = fmaf(x, w.y, acc[v*4+1]);
            acc[v*4+2] = fmaf(x, w.z, acc[v*4+2]);
            acc[v*4+3] = fmaf(x, w.w, acc[v*4+3]);
        }
    }
#pragma unroll
    for (int u = 0; u < 16; u++) sh1[e][o0 + u] = fmaxf(acc[u], 0.f);
    __syncthreads();

#pragma unroll
    for (int u = 0; u < 16; u++) acc[u] = __ldg(&b1b[o0 + u]);
#pragma unroll 8
    for (int k = 0; k < 64; k++) {
        float h = sh1[e][k];
#pragma unroll
        for (int v = 0; v < 4; v++) {
            float4 w = *(const float4*)&sW1b[k * 64 + o0 + v * 4];
            acc[v*4+0] = fmaf(h, w.x, acc[v*4+0]);
            acc[v*4+1] = fmaf(h, w.y, acc[v*4+1]);
            acc[v*4+2] = fmaf(h, w.z, acc[v*4+2]);
            acc[v*4+3] = fmaf(h, w.w, acc[v*4+3]);
        }
    }
    int base = d * FEAT + o0;
#pragma unroll
    for (int u = 0; u < 16; u++) {
        float v = fmaxf(acc[u], 0.f);   // >= 0 : int order == float order
        atomicMax((int*)(g_x1 + base + u), __float_as_int(v));
    }
}

// ---------------- squared norms ---------------------------------------------
__global__ void k_sq() {
    int i = blockIdx.x * blockDim.x + threadIdx.x;
    if (i < N_PTS) {
        const float4* r = (const float4*)(g_x1 + (size_t)i * 64);
        float s = 0.f;
#pragma unroll
        for (int c = 0; c < 16; c++) {
            float4 v = r[c];
            s += v.x * v.x + v.y * v.y + v.z * v.z + v.w * v.w;
        }
        g_sq[i] = s;
    }
}

// ---------------- stage 2: fused distance GEMM + top-16 ---------------------
// block: 128 threads, 32 queries; candidate tiles of 64; 4x4 register tile.
__global__ void __launch_bounds__(128) k_knn() {
    __shared__ float Qs[64][32];    // [k][q]  8 KB
    __shared__ float Bs[64][64];    // [k][c] 16 KB
    __shared__ float Ds[32][65];    // 8.3 KB
    __shared__ float ssq[64];

    int t  = threadIdx.x;
    int qb = blockIdx.x * 32;

    {   // load Q transposed
        int r = t >> 2, part = t & 3;
        const float4* src = (const float4*)(g_x1 + (size_t)(qb + r) * 64);
#pragma unroll
        for (int i = 0; i < 4; i++) {
            float4 v = src[part * 4 + i];
            int k = (part * 4 + i) * 4;
            Qs[k+0][r] = v.x; Qs[k+1][r] = v.y; Qs[k+2][r] = v.z; Qs[k+3][r] = v.w;
        }
    }

    unsigned long long lst[16];
#pragma unroll
    for (int i = 0; i < 16; i++) lst[i] = 0xFFFFFFFFFFFFFFFFull;

    int tx = t & 15, ty = t >> 4;
    int c0 = tx * 4, q0 = ty * 4;

    const int NT = (N_PTS + 63) / 64;   // 313
    for (int tt = 0; tt < NT; tt++) {
        int j0 = tt * 64;
        __syncthreads();   // previous tile's Ds consumed, Bs free
        {   // load candidate tile transposed
            int c  = t >> 1, hf = t & 1;
            int j  = min(j0 + c, N_PTS - 1);
            const float4* src = (const float4*)(g_x1 + (size_t)j * 64);
#pragma unroll
            for (int i = 0; i < 8; i++) {
                float4 v = src[hf * 8 + i];
                int k = hf * 32 + i * 4;
                Bs[k+0][c] = v.x; Bs[k+1][c] = v.y; Bs[k+2][c] = v.z; Bs[k+3][c] = v.w;
            }
            if (hf == 0) ssq[c] = g_sq[j];
        }
        __syncthreads();

        float acc[4][4];
#pragma unroll
        for (int u = 0; u < 4; u++)
#pragma unroll
            for (int v = 0; v < 4; v++) acc[u][v] = 0.f;

#pragma unroll 8
        for (int k = 0; k < 64; k++) {
            float4 qv = *(const float4*)&Qs[k][q0];
            float4 bv = *(const float4*)&Bs[k][c0];
            float q[4] = {qv.x, qv.y, qv.z, qv.w};
            float b[4] = {bv.x, bv.y, bv.z, bv.w};
#pragma unroll
            for (int u = 0; u < 4; u++)
#pragma unroll
                for (int v = 0; v < 4; v++)
                    acc[u][v] = fmaf(q[u], b[v], acc[u][v]);
        }
#pragma unroll
        for (int u = 0; u < 4; u++)
#pragma unroll
            for (int v = 0; v < 4; v++)
                Ds[q0 + u][c0 + v] = fmaf(-2.f, acc[u][v], ssq[c0 + v]);
        __syncthreads();

        if (t < 32) {   // selection: thread t owns query qb+t
            int cmax = min(64, N_PTS - j0);
            for (int c = 0; c < cmax; c++) {
                float d = Ds[t][c];
                unsigned long long key =
                    ((unsigned long long)enc_f(d) << 32) | (unsigned)(j0 + c);
                if (key < lst[15]) {
                    lst[15] = key;
#pragma unroll
                    for (int p = 15; p >= 1; p--) {
                        if (lst[p] < lst[p-1]) {
                            unsigned long long tmp = lst[p];
                            lst[p] = lst[p-1]; lst[p-1] = tmp;
                        }
                    }
                }
            }
        }
    }
    if (t < 32) {
#pragma unroll
        for (int i = 0; i < 16; i++)
            g_nbr[(size_t)(qb + t) * 16 + i] = (int)(lst[i] & 0xffffffffu);
    }
}

// ---------------- stage 3: pair MLP (128->64->64, ReLU) + max over K --------
// block: 256 threads, 64 pair-rows (= 4 points).
__global__ void __launch_bounds__(256) k_pair(
    const float* __restrict__ W2a, const float* __restrict__ b2a,
    const float* __restrict__ W2b, const float* __restrict__ b2b)
{
    __shared__ float sT[128][66];   // transposed activations, 33.8 KB
    __shared__ float sW[32][64];    // weight chunk, 8 KB

    int t = threadIdx.x;
    int r = t >> 2, part = t & 3, o0 = part * 16;
    size_t row = (size_t)blockIdx.x * 64 + r;
    int n = (int)(row >> 4);
    int j = g_nbr[row];

    {   // stage [xi, xj-xi] transposed
        const float4* xi4 = (const float4*)(g_x1 + (size_t)n * 64);
        const float4* xj4 = (const float4*)(g_x1 + (size_t)j * 64);
#pragma unroll
        for (int i = 0; i < 4; i++) {
            float4 a = xi4[part * 4 + i];
            float4 b = xj4[part * 4 + i];
            int k = (part * 4 + i) * 4;
            sT[k+0][r] = a.x;  sT[k+1][r] = a.y;  sT[k+2][r] = a.z;  sT[k+3][r] = a.w;
            sT[64+k+0][r] = b.x - a.x; sT[64+k+1][r] = b.y - a.y;
            sT[64+k+2][r] = b.z - a.z; sT[64+k+3][r] = b.w - a.w;
        }
    }

    float acc[16];
#pragma unroll
    for (int u = 0; u < 16; u++) acc[u] = __ldg(&b2a[o0 + u]);

    for (int ch = 0; ch < 4; ch++) {            // layer 1: k in 4 chunks of 32
        __syncthreads();
        {
            const float4* wsrc = (const float4*)(W2a) + ch * 512;
            float4* wdst = (float4*)sW;
            wdst[t] = wsrc[t];
            wdst[t + 256] = wsrc[t + 256];
        }
        __syncthreads();
#pragma unroll 8
        for (int kk = 0; kk < 32; kk++) {
            float x = sT[ch * 32 + kk][r];
#pragma unroll
            for (int v = 0; v < 4; v++) {
                float4 w = *(const float4*)&sW[kk][o0 + v * 4];
                acc[v*4+0] = fmaf(x, w.x, acc[v*4+0]);
                acc[v*4+1] = fmaf(x, w.y, acc[v*4+1]);
                acc[v*4+2] = fmaf(x, w.z, acc[v*4+2]);
                acc[v*4+3] = fmaf(x, w.w, acc[v*4+3]);
            }
        }
    }
    __syncthreads();
#pragma unroll
    for (int u = 0; u < 16; u++) sT[o0 + u][r] = fmaxf(acc[u], 0.f);  // hidden

#pragma unroll
    for (int u = 0; u < 16; u++) acc[u] = __ldg(&b2b[o0 + u]);
    for (int ch = 0; ch < 2; ch++) {            // layer 2
        __syncthreads();
        {
            const float4* wsrc = (const float4*)(W2b) + ch * 512;
            float4* wdst = (float4*)sW;
            wdst[t] = wsrc[t];
            wdst[t + 256] = wsrc[t + 256];
        }
        __syncthreads();
#pragma unroll 8
        for (int kk = 0; kk < 32; kk++) {
            float x = sT[ch * 32 + kk][r];
#pragma unroll
            for (int v = 0; v < 4; v++) {
                float4 w = *(const float4*)&sW[kk][o0 + v * 4];
                acc[v*4+0] = fmaf(x, w.x, acc[v*4+0]);
                acc[v*4+1] = fmaf(x, w.y, acc[v*4+1]);
                acc[v*4+2] = fmaf(x, w.z, acc[v*4+2]);
                acc[v*4+3] = fmaf(x, w.w, acc[v*4+3]);
            }
        }
    }
    __syncthreads();
#pragma unroll
    for (int u = 0; u < 16; u++) sT[o0 + u][r] = fmaxf(acc[u], 0.f);  // msg2
    __syncthreads();

    {   // max over the 16 neighbors of each of the 4 points
        int p = t >> 6, f = t & 63;
        float m = sT[f][p * 16];
#pragma unroll
        for (int kk = 1; kk < 16; kk++) m = fmaxf(m, sT[f][p * 16 + kk]);
        g_x2[((size_t)blockIdx.x * 4 + p) * 64 + f] = m;
    }
}

// ---------------- stage 4: fused head (We_r -> Wp -> relu(Wr1) -> Wr2) ------
// grid: (313, 4); block 256 threads, 64 output rows.
__global__ void __launch_bounds__(256) k_head(
    const float* __restrict__ We,  const float* __restrict__ be,
    const float* __restrict__ Wp,  const float* __restrict__ bp,
    const float* __restrict__ Wr1, const float* __restrict__ br1,
    const float* __restrict__ Wr2, const float* __restrict__ br2,
    float* __restrict__ out)
{
    __shared__ float sT[64][66];   // 16.9 KB
    __shared__ float sW[64][64];   // 16 KB

    int t = threadIdx.x;
    int r = t >> 2, part = t & 3, o0 = part * 16;
    int rr = blockIdx.y;
    int n  = blockIdx.x * 64 + r;
    int nl = min(n, N_PTS - 1);

    {   // stage x2 row transposed
        const float4* src = (const float4*)(g_x2 + (size_t)nl * 64);
#pragma unroll
        for (int i = 0; i < 4; i++) {
            float4 v = src[part * 4 + i];
            int k = (part * 4 + i) * 4;
            sT[k+0][r] = v.x; sT[k+1][r] = v.y; sT[k+2][r] = v.z; sT[k+3][r] = v.w;
        }
    }
    {   // sW = We[:, rr*64 : rr*64+64]
        int kr = t >> 2, q = t & 3;
#pragma unroll
        for (int i = 0; i < 4; i++)
            *(float4*)&sW[kr][q * 16 + i * 4] =
                *(const float4*)(We + (size_t)kr * 256 + rr * 64 + q * 16 + i * 4);
    }
    __syncthreads();

    float acc[16];
#pragma unroll
    for (int u = 0; u < 16; u++) acc[u] = __ldg(&be[rr * 64 + o0 + u]);
#pragma unroll 8
    for (int k = 0; k < 64; k++) {
        float x = sT[k][r];
#pragma unroll
        for (int v = 0; v < 4; v++) {
            float4 w = *(const float4*)&sW[k][o0 + v * 4];
            acc[v*4+0] = fmaf(x, w.x, acc[v*4+0]);
            acc[v*4+1] = fmaf(x, w.y, acc[v*4+1]);
            acc[v*4+2] = fmaf(x, w.z, acc[v*4+2]);
            acc[v*4+3] = fmaf(x, w.w, acc[v*4+3]);
        }
    }
    __syncthreads();
#pragma unroll
    for (int u = 0; u < 16; u++) sT[o0 + u][r] = acc[u];     // xe (no relu)
    {   // sW = Wp
        int kr = t >> 2, q = t & 3;
#pragma unroll
        for (int i = 0; i < 4; i++)
            *(float4*)&sW[kr][q * 16 + i * 4] =
                *(const float4*)(Wp + (size_t)kr * 64 + q * 16 + i * 4);
    }
    __syncthreads();

#pragma unroll
    for (int u = 0; u < 16; u++) acc[u] = __ldg(&bp[o0 + u]);
#pragma unroll 8
    for (int k = 0; k < 64; k++) {
        float x = sT[k][r];
#pragma unroll
        for (int v = 0; v < 4; v++) {
            float4 w = *(const float4*)&sW[k][o0 + v * 4];
            acc[v*4+0] = fmaf(x, w.x, acc[v*4+0]);
            acc[v*4+1] = fmaf(x, w.y, acc[v*4+1]);
            acc[v*4+2] = fmaf(x, w.z, acc[v*4+2]);
            acc[v*4+3] = fmaf(x, w.w, acc[v*4+3]);
        }
    }
    __syncthreads();
#pragma unroll
    for (int u = 0; u < 16; u++) sT[o0 + u][r] = acc[u];     // feat (no relu)
    {   // sW = Wr1
        int kr = t >> 2, q = t & 3;
#pragma unroll
        for (int i = 0; i < 4; i++)
            *(float4*)&sW[kr][q * 16 + i * 4] =
                *(const float4*)(Wr1 + (size_t)kr * 64 + q * 16 + i * 4);
    }
    __syncthreads();

#pragma unroll
    for (int u = 0; u < 16; u++) acc[u] = __ldg(&br1[o0 + u]);
#pragma unroll 8
    for (int k = 0; k < 64; k++) {
        float x = sT[k][r];
#pragma unroll
        for (int v = 0; v < 4; v++) {
            float4 w = *(const float4*)&sW[k][o0 + v * 4];
            acc[v*4+0] = fmaf(x, w.x, acc[v*4+0]);
            acc[v*4+1] = fmaf(x, w.y, acc[v*4+1]);
            acc[v*4+2] = fmaf(x, w.z, acc[v*4+2]);
            acc[v*4+3] = fmaf(x, w.w, acc[v*4+3]);
        }
    }
    __syncthreads();
#pragma unroll
    for (int u = 0; u < 16; u++) sT[o0 + u][r] = fmaxf(acc[u], 0.f);  // h = relu
    if (t < 192) ((float*)sW)[t] = Wr2[t];            // stage Wr2 (64x3)
    if (t >= 192 && t < 195) ((float*)sW)[t] = br2[t - 192];
    __syncthreads();

    if (part < 3 && n < N_PTS) {
        float y = ((float*)sW)[192 + part];
#pragma unroll 8
        for (int k = 0; k < 64; k++)
            y = fmaf(sT[k][r], ((float*)sW)[k * 3 + part], y);
        out[((size_t)rr * N_PTS + n) * 3 + part] = y;
    }
}

// ---------------- launch -----------------------------------------------------
extern "C" void kernel_launch(void* const* d_in, const int* in_sizes, int n_in,
                              void* d_out, int out_size) {
    const float* pts = (const float*)d_in[0];
    const float* W1a = (const float*)d_in[1];
    const float* b1a = (const float*)d_in[2];
    const float* W1b = (const float*)d_in[3];
    const float* b1b = (const float*)d_in[4];
    const float* W2a = (const float*)d_in[5];
    const float* b2a = (const float*)d_in[6];
    const float* W2b = (const float*)d_in[7];
    const float* b2b = (const float*)d_in[8];
    const float* We  = (const float*)d_in[9];
    const float* be  = (const float*)d_in[10];
    const float* Wp  = (const float*)d_in[11];
    const float* bp  = (const float*)d_in[12];
    const float* Wr1 = (const float*)d_in[13];
    const float* br1 = (const float*)d_in[14];
    const float* Wr2 = (const float*)d_in[15];
    const float* br2 = (const float*)d_in[16];
    const int*   ei  = (const int*)d_in[17];
    float* out = (float*)d_out;

    k_zero_x1<<<(N_PTS * FEAT + 255) / 256, 256>>>();
    k_edge<<<E_EDGES / 64, 256>>>(pts, ei, W1a, b1a, W1b, b1b);
    k_sq<<<(N_PTS + 255) / 256, 256>>>();
    k_knn<<<N_PTS / 32, 128>>>();
    k_pair<<<(N_PTS * KNN) / 64, 256>>>(W2a, b2a, W2b, b2b);
    k_head<<<dim3((N_PTS + 63) / 64, R_REP), 256>>>(We, be, Wp, bp, Wr1, br1,
                                                    Wr2, br2, out);
}